// round 12
// baseline (speedup 1.0000x reference)
#include <cuda_runtime.h>
#include <math.h>
#include <stdint.h>

#define VIEWS 8
#define SEQL  2048
#define HID   1024
#define ATT   128
#define SCALE 0.08838834764831845f   /* 1/sqrt(128) */

// ---------------- scratch (device globals: no allocations allowed) ----------
__device__ float g_qh[VIEWS * SEQL * ATT];   // tf32-rounded
__device__ float g_kh[VIEWS * SEQL * ATT];   // tf32-rounded
__device__ float g_vh[VIEWS * SEQL * ATT];   // tf32-rounded
__device__ float g_x [SEQL * HID];           // x transposed to [S, V*A]
__device__ float g_zero[ATT];                // zero bias

// ---------------------------------------------------------------------------
// helpers
// ---------------------------------------------------------------------------
__device__ __forceinline__ float tf32r(float x) {
    uint32_t u;
    asm("cvt.rna.tf32.f32 %0, %1;" : "=r"(u) : "f"(x));
    return __uint_as_float(u);
}

__device__ __forceinline__ void mma_tf32(float* d,
    uint32_t a0, uint32_t a1, uint32_t a2, uint32_t a3,
    uint32_t b0, uint32_t b1)
{
    asm volatile(
        "mma.sync.aligned.m16n8k8.row.col.f32.tf32.tf32.f32 "
        "{%0,%1,%2,%3},{%4,%5,%6,%7},{%8,%9},{%0,%1,%2,%3};\n"
        : "+f"(d[0]), "+f"(d[1]), "+f"(d[2]), "+f"(d[3])
        : "r"(a0), "r"(a1), "r"(a2), "r"(a3), "r"(b0), "r"(b1));
}

__device__ __forceinline__ uint32_t lduf(const float* p) {
    return __float_as_uint(*p);
}
__device__ __forceinline__ uint32_t smem_u32(const void* p) {
    uint32_t a;
    asm("{ .reg .u64 t; cvta.to.shared.u64 t, %1; cvt.u32.u64 %0, t; }"
        : "=r"(a) : "l"(p));
    return a;
}
__device__ __forceinline__ void cpasync16(uint32_t dst, const void* src) {
    asm volatile("cp.async.cg.shared.global [%0], [%1], 16;\n" :: "r"(dst), "l"(src));
}
#define CP_COMMIT() asm volatile("cp.async.commit_group;\n" ::: "memory")
#define CP_WAIT0()  asm volatile("cp.async.wait_group 0;\n"  ::: "memory")
#define CP_WAIT1()  asm volatile("cp.async.wait_group 1;\n"  ::: "memory")

// ============================================================================
// TF32 mma.sync GEMM, MRx128 block tile (MR = 64 or 128), 256 threads,
// 2-stage cp.async pipeline, 2 CTAs/SM.
// A: [..][lda] rm (pre-offset). B: [Ktot][ldb] rm. C = (A@B + bias) * mul.
// Warp tile: (MR/4) x 64.  BK = 32.  TF32 rounding at fragment load.
// ============================================================================
#define GLDA 36
#define GLDB 136

template<int MR, bool RA, bool RB>
__device__ __forceinline__ void sgemm2(
    const float* __restrict__ A, int lda,
    const float* __restrict__ B, int ldb,
    const float* __restrict__ bias,
    float* __restrict__ C, int ldc,
    int Ktot, float mul, bool round_out)
{
    extern __shared__ float dynsm[];
    constexpr int AST = MR * GLDA;
    constexpr int STG = AST + 32 * GLDB;
    constexpr int MT  = MR / 64;          // m-tiles (of 16 rows) per warp
    constexpr int NA  = MR / 32;          // A float4 loads per thread

    const int tid  = threadIdx.x;
    const int wid  = tid >> 5;
    const int lane = tid & 31;
    const int g    = lane >> 2;
    const int tig  = lane & 3;

    const int m0 = (wid & 3) * (MR / 4);
    const int n0 = (wid >> 2) * 64;

    const int niter = Ktot >> 5;

    auto issue = [&](int it) {
        const int k0 = it << 5;
        float* As = dynsm + (it & 1) * STG;
        float* Bs = As + AST;
        const uint32_t sA = smem_u32(As), sB = smem_u32(Bs);
#pragma unroll
        for (int i = 0; i < NA; i++) {
            const int idx = tid + i * 256;
            const int r = idx >> 3, c4 = (idx & 7) << 2;
            cpasync16(sA + (uint32_t)(r * GLDA + c4) * 4,
                      &A[(size_t)r * lda + k0 + c4]);
        }
#pragma unroll
        for (int i = 0; i < 4; i++) {
            const int idx = tid + i * 256;
            const int r = idx >> 5, c4 = (idx & 31) << 2;
            cpasync16(sB + (uint32_t)(r * GLDB + c4) * 4,
                      &B[(size_t)(k0 + r) * ldb + c4]);
        }
        CP_COMMIT();
    };

    float acc[MT][8][4];
#pragma unroll
    for (int mt = 0; mt < MT; mt++)
#pragma unroll
        for (int nt = 0; nt < 8; nt++)
#pragma unroll
            for (int i = 0; i < 4; i++) acc[mt][nt][i] = 0.f;

    issue(0);
    issue(1);

    for (int it = 0; it < niter; it++) {
        if (it + 1 < niter) CP_WAIT1(); else CP_WAIT0();
        __syncthreads();

        const float* As = dynsm + (it & 1) * STG;
        const float* Bs = As + AST;

#pragma unroll
        for (int kk = 0; kk < 32; kk += 8) {
            uint32_t a[MT][4];
#pragma unroll
            for (int mt = 0; mt < MT; mt++) {
                const int r = m0 + mt * 16;
                float x0 = As[(r + g)     * GLDA + kk + tig];
                float x1 = As[(r + g + 8) * GLDA + kk + tig];
                float x2 = As[(r + g)     * GLDA + kk + tig + 4];
                float x3 = As[(r + g + 8) * GLDA + kk + tig + 4];
                if (RA) { x0 = tf32r(x0); x1 = tf32r(x1); x2 = tf32r(x2); x3 = tf32r(x3); }
                a[mt][0] = __float_as_uint(x0);
                a[mt][1] = __float_as_uint(x1);
                a[mt][2] = __float_as_uint(x2);
                a[mt][3] = __float_as_uint(x3);
            }
#pragma unroll
            for (int nt = 0; nt < 8; nt++) {
                const int nc = n0 + nt * 8 + g;
                float y0 = Bs[(kk + tig)     * GLDB + nc];
                float y1 = Bs[(kk + tig + 4) * GLDB + nc];
                if (RB) { y0 = tf32r(y0); y1 = tf32r(y1); }
                const uint32_t b0 = __float_as_uint(y0);
                const uint32_t b1 = __float_as_uint(y1);
#pragma unroll
                for (int mt = 0; mt < MT; mt++)
                    mma_tf32(acc[mt][nt], a[mt][0], a[mt][1], a[mt][2], a[mt][3], b0, b1);
            }
        }

        __syncthreads();
        if (it + 2 < niter) issue(it + 2);
    }

    // epilogue
#pragma unroll
    for (int mt = 0; mt < MT; mt++) {
        const int r = m0 + mt * 16;
#pragma unroll
        for (int nt = 0; nt < 8; nt++) {
            const int col = n0 + nt * 8 + tig * 2;
            const float b0 = bias[col], b1 = bias[col + 1];
            float2 o0, o1;
            o0.x = (acc[mt][nt][0] + b0) * mul;  o0.y = (acc[mt][nt][1] + b1) * mul;
            o1.x = (acc[mt][nt][2] + b0) * mul;  o1.y = (acc[mt][nt][3] + b1) * mul;
            if (round_out) {
                o0.x = tf32r(o0.x); o0.y = tf32r(o0.y);
                o1.x = tf32r(o1.x); o1.y = tf32r(o1.y);
            }
            *(float2*)&C[(size_t)(r + g)     * ldc + col] = o0;
            *(float2*)&C[(size_t)(r + g + 8) * ldc + col] = o1;
        }
    }
}

#define SMEM_G128 ((128 * GLDA + 32 * GLDB) * 2 * 4)   // 71680
#define SMEM_G64  ((64  * GLDA + 32 * GLDB) * 2 * 4)   // 53248

// ---------------------------------------------------------------------------
// Kernel 1: fused QKV projection.  grid (16 Mtiles, 8 views, 3 proj)
// ---------------------------------------------------------------------------
__global__ void __launch_bounds__(256, 2) proj_kernel(
    const float* __restrict__ q, const float* __restrict__ k,
    const float* __restrict__ v,
    const float* __restrict__ wq, const float* __restrict__ bq,
    const float* __restrict__ wk, const float* __restrict__ bk,
    const float* __restrict__ wv, const float* __restrict__ bv)
{
    const int view = blockIdx.y;
    const int pz   = blockIdx.z;
    const float *A, *W, *bias;
    float* O;
    float mul = 1.0f;
    if (pz == 0)      { A = q; W = wq; bias = bq; O = g_qh; mul = SCALE; }
    else if (pz == 1) { A = k; W = wk; bias = bk; O = g_kh; }
    else              { A = v; W = wv; bias = bv; O = g_vh; }

    A += (size_t)view * SEQL * HID;
    O += (size_t)view * SEQL * ATT;
    const int row0 = blockIdx.x * 128;
    sgemm2<128, true, true>(A + (size_t)row0 * HID, HID, W, ATT, bias,
                            O + (size_t)row0 * ATT, ATT, HID, mul, true);
}

// ---------------------------------------------------------------------------
// Kernel 1b: bias GEMM.  g_x[q][v*A+a] = attn_bias[v,q,:] @ vh[v,:,a]
// grid (32 Mtiles of 64, 8 views) = 256 CTAs.
// ---------------------------------------------------------------------------
__global__ void __launch_bounds__(256, 2) biasv_kernel(const float* __restrict__ attn_bias)
{
    const int view = blockIdx.y;
    const int row0 = blockIdx.x * 64;
    const float* A = attn_bias + (size_t)view * SEQL * SEQL + (size_t)row0 * SEQL;
    const float* B = g_vh + (size_t)view * SEQL * ATT;
    float* C = g_x + (size_t)row0 * HID + view * ATT;
    sgemm2<64, true, false>(A, SEQL, B, ATT, g_zero, C, HID, SEQL, 1.0f, false);
}

// ---------------------------------------------------------------------------
// Kernel 3: out = x @ wo + bo.  grid (32 Mtiles of 64, 8 Ntiles) = 256 CTAs.
// ---------------------------------------------------------------------------
__global__ void __launch_bounds__(256, 2) out_kernel(
    const float* __restrict__ wo, const float* __restrict__ bo,
    float* __restrict__ out)
{
    const int row0 = blockIdx.x * 64;
    const int col0 = blockIdx.y * 128;
    sgemm2<64, true, true>(g_x + (size_t)row0 * HID, HID,
                           wo + col0, HID, bo + col0,
                           out + (size_t)row0 * HID + col0, HID, HID, 1.0f, false);
}

// ---------------------------------------------------------------------------
// Kernel 2: FA2-style attention, register softmax + REGISTER-RESIDENT Q frags,
//   128 threads (4 warps), BQ=64, BK=32, double-buffered cp.async K/V.
//   grid (32 q-tiles, 8 views) = 256 CTAs, 2/SM.
//   Epilogue adds into g_x (holds bias@V term from biasv_kernel).
// ---------------------------------------------------------------------------
#define BQ    64
#define BK    32
#define NT_KT (SEQL / BK)    // 64
#define LDQ   132
#define LDV   136
#define KSTG  (BK * LDQ)
#define VSTG  (BK * LDV)
#define SMEM_ATTN_FLOATS (BQ * LDQ + 2 * KSTG + 2 * VSTG)
#define SMEM_ATTN_BYTES  (SMEM_ATTN_FLOATS * 4)

__global__ void __launch_bounds__(128) attn_kernel()
{
    extern __shared__ float sm[];
    float* Qs = sm;
    float* Kb = Qs + BQ * LDQ;
    float* Vb = Kb + 2 * KSTG;

    const int tid  = threadIdx.x;
    const int wid  = tid >> 5;
    const int lane = tid & 31;
    const int g    = lane >> 2;
    const int tig  = lane & 3;

    const int view = blockIdx.y;
    const int q0   = blockIdx.x * BQ;

    const float* qh = g_qh + (size_t)view * SEQL * ATT + (size_t)q0 * ATT;
    const float* kh = g_kh + (size_t)view * SEQL * ATT;
    const float* vh = g_vh + (size_t)view * SEQL * ATT;

    const uint32_t sQ = smem_u32(Qs);
    const uint32_t sK = smem_u32(Kb);
    const uint32_t sV = smem_u32(Vb);

    auto issueKV = [&](int it) {
        const int buf = it & 1;
        const float* kbase = kh + (size_t)(it * BK) * ATT;
        const float* vbase = vh + (size_t)(it * BK) * ATT;
#pragma unroll
        for (int i = 0; i < 8; i++) {
            const int idx = tid + i * 128;
            const int r = idx >> 5, c4 = (idx & 31) << 2;
            cpasync16(sK + (uint32_t)(buf * KSTG + r * LDQ + c4) * 4,
                      &kbase[(size_t)r * ATT + c4]);
            cpasync16(sV + (uint32_t)(buf * VSTG + r * LDV + c4) * 4,
                      &vbase[(size_t)r * ATT + c4]);
        }
        CP_COMMIT();
    };

    // prologue: group0 = Q + KV(0); group1 = KV(1)
    {
#pragma unroll
        for (int i = 0; i < 16; i++) {
            const int idx = tid + i * 128;
            const int r = idx >> 5, c4 = (idx & 31) << 2;
            cpasync16(sQ + (uint32_t)(r * LDQ + c4) * 4, &qh[(size_t)r * ATT + c4]);
        }
#pragma unroll
        for (int i = 0; i < 8; i++) {
            const int idx = tid + i * 128;
            const int r = idx >> 5, c4 = (idx & 31) << 2;
            cpasync16(sK + (uint32_t)(r * LDQ + c4) * 4, &kh[(size_t)r * ATT + c4]);
            cpasync16(sV + (uint32_t)(r * LDV + c4) * 4, &vh[(size_t)r * ATT + c4]);
        }
        CP_COMMIT();
        issueKV(1);
    }

    const int m0 = wid * 16;

    // ---- hoist Q fragments to registers (Q invariant across kt loop) ----
    uint32_t qf[16][4];
    CP_WAIT1();               // group0 (Q + KV0) complete
    __syncthreads();
#pragma unroll
    for (int s = 0; s < 16; s++) {
        const int kk = s * 8;
        qf[s][0] = lduf(&Qs[(m0 + g)     * LDQ + kk + tig]);
        qf[s][1] = lduf(&Qs[(m0 + g + 8) * LDQ + kk + tig]);
        qf[s][2] = lduf(&Qs[(m0 + g)     * LDQ + kk + tig + 4]);
        qf[s][3] = lduf(&Qs[(m0 + g + 8) * LDQ + kk + tig + 4]);
    }

    float oacc[16][4];
#pragma unroll
    for (int nt = 0; nt < 16; nt++)
#pragma unroll
        for (int i = 0; i < 4; i++) oacc[nt][i] = 0.f;

    float mst0 = -3.0e38f, mst1 = -3.0e38f;
    float lst0 = 0.f,      lst1 = 0.f;

    const int srcA = (g << 2) + (tig >> 1);
    const int srcB = srcA + 2;
    const bool odd = (tig & 1);

    for (int kt = 0; kt < NT_KT; kt++) {
        if (kt + 1 < NT_KT) CP_WAIT1(); else CP_WAIT0();
        __syncthreads();

        const float* Ks = Kb + (kt & 1) * KSTG;
        const float* Vs = Vb + (kt & 1) * VSTG;

        // ---- phase 1: S(16x32 per warp) = Q @ K^T ----
        float sacc[4][4];
#pragma unroll
        for (int j = 0; j < 4; j++)
#pragma unroll
            for (int i = 0; i < 4; i++) sacc[j][i] = 0.f;

#pragma unroll
        for (int s = 0; s < 16; s++) {
            const int kk = s * 8;
#pragma unroll
            for (int j = 0; j < 4; j++) {
                const int nr = j * 8 + g;
                const uint32_t b0 = lduf(&Ks[nr * LDQ + kk + tig]);
                const uint32_t b1 = lduf(&Ks[nr * LDQ + kk + tig + 4]);
                mma_tf32(sacc[j], qf[s][0], qf[s][1], qf[s][2], qf[s][3], b0, b1);
            }
        }

        // ---- phase 2: register online softmax ----
        {
            float mx0 = -3.0e38f, mx1 = -3.0e38f;
#pragma unroll
            for (int j = 0; j < 4; j++) {
                mx0 = fmaxf(mx0, fmaxf(sacc[j][0], sacc[j][1]));
                mx1 = fmaxf(mx1, fmaxf(sacc[j][2], sacc[j][3]));
            }
            mx0 = fmaxf(mx0, __shfl_xor_sync(0xffffffffu, mx0, 1));
            mx0 = fmaxf(mx0, __shfl_xor_sync(0xffffffffu, mx0, 2));
            mx1 = fmaxf(mx1, __shfl_xor_sync(0xffffffffu, mx1, 1));
            mx1 = fmaxf(mx1, __shfl_xor_sync(0xffffffffu, mx1, 2));

            const float mnew0 = fmaxf(mst0, mx0);
            const float mnew1 = fmaxf(mst1, mx1);
            const float corr0 = __expf(mst0 - mnew0);
            const float corr1 = __expf(mst1 - mnew1);
            mst0 = mnew0; mst1 = mnew1;

            float s0 = 0.f, s1 = 0.f;
#pragma unroll
            for (int j = 0; j < 4; j++) {
                float e;
                e = __expf(sacc[j][0] - mnew0); s0 += e; sacc[j][0] = tf32r(e);
                e = __expf(sacc[j][1] - mnew0); s0 += e; sacc[j][1] = tf32r(e);
                e = __expf(sacc[j][2] - mnew1); s1 += e; sacc[j][2] = tf32r(e);
                e = __expf(sacc[j][3] - mnew1); s1 += e; sacc[j][3] = tf32r(e);
            }
            s0 += __shfl_xor_sync(0xffffffffu, s0, 1);
            s0 += __shfl_xor_sync(0xffffffffu, s0, 2);
            s1 += __shfl_xor_sync(0xffffffffu, s1, 1);
            s1 += __shfl_xor_sync(0xffffffffu, s1, 2);
            lst0 = lst0 * corr0 + s0;
            lst1 = lst1 * corr1 + s1;

#pragma unroll
            for (int nt = 0; nt < 16; nt++) {
                oacc[nt][0] *= corr0; oacc[nt][1] *= corr0;
                oacc[nt][2] *= corr1; oacc[nt][3] *= corr1;
            }
        }

        // ---- phase 3: oacc += P @ V  (register shfl transpose) ----
#pragma unroll
        for (int jk = 0; jk < 4; jk++) {
            const float e0 = __shfl_sync(0xffffffffu, sacc[jk][0], srcA);
            const float e1 = __shfl_sync(0xffffffffu, sacc[jk][1], srcA);
            const float f0 = __shfl_sync(0xffffffffu, sacc[jk][2], srcA);
            const float f1 = __shfl_sync(0xffffffffu, sacc[jk][3], srcA);
            const float e2 = __shfl_sync(0xffffffffu, sacc[jk][0], srcB);
            const float e3 = __shfl_sync(0xffffffffu, sacc[jk][1], srcB);
            const float f2 = __shfl_sync(0xffffffffu, sacc[jk][2], srcB);
            const float f3 = __shfl_sync(0xffffffffu, sacc[jk][3], srcB);
            const uint32_t a0 = __float_as_uint(odd ? e1 : e0);
            const uint32_t a1 = __float_as_uint(odd ? f1 : f0);
            const uint32_t a2 = __float_as_uint(odd ? e3 : e2);
            const uint32_t a3 = __float_as_uint(odd ? f3 : f2);
#pragma unroll
            for (int nt = 0; nt < 16; nt++) {
                const int nc = nt * 8 + g;
                const uint32_t b0 = lduf(&Vs[(jk * 8 + tig)     * LDV + nc]);
                const uint32_t b1 = lduf(&Vs[(jk * 8 + tig + 4) * LDV + nc]);
                mma_tf32(oacc[nt], a0, a1, a2, a3, b0, b1);
            }
        }

        __syncthreads();
        if (kt + 2 < NT_KT) issueKV(kt + 2);
    }

    // ---- epilogue: g_x += oacc / l  (g_x holds bias@V term) ----
    const float inv0 = 1.f / lst0;
    const float inv1 = 1.f / lst1;
    float* xr0 = g_x + (size_t)(q0 + m0 + g)     * HID + view * ATT;
    float* xr1 = g_x + (size_t)(q0 + m0 + g + 8) * HID + view * ATT;
#pragma unroll
    for (int nt = 0; nt < 16; nt++) {
        const int col = nt * 8 + tig * 2;
        float2 x0 = *(const float2*)&xr0[col];
        float2 x1 = *(const float2*)&xr1[col];
        x0.x += oacc[nt][0] * inv0;  x0.y += oacc[nt][1] * inv0;
        x1.x += oacc[nt][2] * inv1;  x1.y += oacc[nt][3] * inv1;
        *(float2*)&xr0[col] = x0;
        *(float2*)&xr1[col] = x1;
    }
}

// ---------------------------------------------------------------------------
extern "C" void kernel_launch(void* const* d_in, const int* in_sizes, int n_in,
                              void* d_out, int out_size)
{
    const float* q  = (const float*)d_in[0];
    const float* k  = (const float*)d_in[1];
    const float* v  = (const float*)d_in[2];
    const float* ab = (const float*)d_in[3];
    const float* wq = (const float*)d_in[4];
    const float* bq = (const float*)d_in[5];
    const float* wk = (const float*)d_in[6];
    const float* bk = (const float*)d_in[7];
    const float* wv = (const float*)d_in[8];
    const float* bv = (const float*)d_in[9];
    const float* wo = (const float*)d_in[10];
    const float* bo = (const float*)d_in[11];
    float* out = (float*)d_out;

    cudaFuncSetAttribute(proj_kernel,  cudaFuncAttributeMaxDynamicSharedMemorySize, SMEM_G128);
    cudaFuncSetAttribute(biasv_kernel, cudaFuncAttributeMaxDynamicSharedMemorySize, SMEM_G64);
    cudaFuncSetAttribute(out_kernel,   cudaFuncAttributeMaxDynamicSharedMemorySize, SMEM_G64);
    cudaFuncSetAttribute(attn_kernel,  cudaFuncAttributeMaxDynamicSharedMemorySize, SMEM_ATTN_BYTES);

    proj_kernel<<<dim3(SEQL / 128, VIEWS, 3), 256, SMEM_G128>>>(
        q, k, v, wq, bq, wk, bk, wv, bv);
    biasv_kernel<<<dim3(SEQL / 64, VIEWS), 256, SMEM_G64>>>(ab);
    attn_kernel<<<dim3(SEQL / BQ, VIEWS), 128, SMEM_ATTN_BYTES>>>();
    out_kernel<<<dim3(SEQL / 64, HID / 128), 256, SMEM_G64>>>(wo, bo, out);
}

// round 13
// speedup vs baseline: 1.0119x; 1.0119x over previous
#include <cuda_runtime.h>
#include <math.h>
#include <stdint.h>

#define VIEWS 8
#define SEQL  2048
#define HID   1024
#define ATT   128
#define SCALE 0.08838834764831845f   /* 1/sqrt(128) */

// ---------------- scratch (device globals: no allocations allowed) ----------
__device__ float g_qh[VIEWS * SEQL * ATT];   // tf32-rounded
__device__ float g_kh[VIEWS * SEQL * ATT];   // tf32-rounded
__device__ float g_vh[VIEWS * SEQL * ATT];   // tf32-rounded
__device__ float g_x [SEQL * HID];           // x transposed to [S, V*A]
__device__ float g_zero[ATT];                // zero bias

// ---------------------------------------------------------------------------
// helpers
// ---------------------------------------------------------------------------
__device__ __forceinline__ float tf32r(float x) {
    uint32_t u;
    asm("cvt.rna.tf32.f32 %0, %1;" : "=r"(u) : "f"(x));
    return __uint_as_float(u);
}

__device__ __forceinline__ void mma_tf32(float* d,
    uint32_t a0, uint32_t a1, uint32_t a2, uint32_t a3,
    uint32_t b0, uint32_t b1)
{
    asm volatile(
        "mma.sync.aligned.m16n8k8.row.col.f32.tf32.tf32.f32 "
        "{%0,%1,%2,%3},{%4,%5,%6,%7},{%8,%9},{%0,%1,%2,%3};\n"
        : "+f"(d[0]), "+f"(d[1]), "+f"(d[2]), "+f"(d[3])
        : "r"(a0), "r"(a1), "r"(a2), "r"(a3), "r"(b0), "r"(b1));
}

__device__ __forceinline__ uint32_t lduf(const float* p) {
    return __float_as_uint(*p);
}
__device__ __forceinline__ uint32_t smem_u32(const void* p) {
    uint32_t a;
    asm("{ .reg .u64 t; cvta.to.shared.u64 t, %1; cvt.u32.u64 %0, t; }"
        : "=r"(a) : "l"(p));
    return a;
}
__device__ __forceinline__ void cpasync16(uint32_t dst, const void* src) {
    asm volatile("cp.async.cg.shared.global [%0], [%1], 16;\n" :: "r"(dst), "l"(src));
}
#define CP_COMMIT() asm volatile("cp.async.commit_group;\n" ::: "memory")
#define CP_WAIT0()  asm volatile("cp.async.wait_group 0;\n"  ::: "memory")
#define CP_WAIT1()  asm volatile("cp.async.wait_group 1;\n"  ::: "memory")

// ============================================================================
// TF32 tensor-core GEMM, 128x128 block, 256 threads (8 warps, 4m x 2n),
// warp tile 32x64, BK=32, 3-stage cp.async smem pipeline.  (R10 config)
// TF32 rounding applied at fragment load when the operand isn't pre-rounded.
// C = (A@B + bias) * mul.
// ============================================================================
#define GLDA 36     // As row stride (pad)
#define GLDB 136    // Bs row stride (pad)
#define STG_F (128 * GLDA + 32 * GLDB)          // floats per stage = 8960
#define SMEM_GEMM_BYTES (3 * STG_F * 4)         // 107520 B

template<bool RA, bool RB>
__device__ __forceinline__ void sgemm_pipe(
    const float* __restrict__ A, int lda,
    const float* __restrict__ B, int ldb,
    const float* __restrict__ bias,
    float* __restrict__ C, int ldc,
    int Ktot, float mul, bool round_out)
{
    extern __shared__ float dynsm[];

    const int tid  = threadIdx.x;
    const int wid  = tid >> 5;
    const int lane = tid & 31;
    const int g    = lane >> 2;
    const int tig  = lane & 3;

    const int m0 = (wid & 3) * 32;
    const int n0 = (wid >> 2) * 64;

    const int ar  = tid >> 3, ac4 = (tid & 7) << 2;
    const int br  = tid >> 5, bc4 = (tid & 31) << 2;

    const int niter = Ktot >> 5;

    auto issue = [&](int it) {
        const int k0 = it << 5;
        float* As = dynsm + (it % 3) * STG_F;
        float* Bs = As + 128 * GLDA;
        const uint32_t sA = smem_u32(As), sB = smem_u32(Bs);
#pragma unroll
        for (int i = 0; i < 4; i++) {
            const int r  = ar + i * 32;
            cpasync16(sA + (uint32_t)(r * GLDA + ac4) * 4,
                      &A[(size_t)r * lda + k0 + ac4]);
            const int rb = br + i * 8;
            cpasync16(sB + (uint32_t)(rb * GLDB + bc4) * 4,
                      &B[(size_t)(k0 + rb) * ldb + bc4]);
        }
        CP_COMMIT();
    };

    float acc[2][8][4];
#pragma unroll
    for (int mt = 0; mt < 2; mt++)
#pragma unroll
        for (int nt = 0; nt < 8; nt++)
#pragma unroll
            for (int i = 0; i < 4; i++) acc[mt][nt][i] = 0.f;

    issue(0);
    if (niter > 1) issue(1);

    for (int it = 0; it < niter; it++) {
        if (it + 1 < niter) CP_WAIT1(); else CP_WAIT0();
        __syncthreads();
        if (it + 2 < niter) issue(it + 2);

        const float* As = dynsm + (it % 3) * STG_F;
        const float* Bs = As + 128 * GLDA;

#pragma unroll
        for (int kk = 0; kk < 32; kk += 8) {
            uint32_t a[2][4];
#pragma unroll
            for (int mt = 0; mt < 2; mt++) {
                const int r = m0 + mt * 16;
                float x0 = As[(r + g)     * GLDA + kk + tig];
                float x1 = As[(r + g + 8) * GLDA + kk + tig];
                float x2 = As[(r + g)     * GLDA + kk + tig + 4];
                float x3 = As[(r + g + 8) * GLDA + kk + tig + 4];
                if (RA) { x0 = tf32r(x0); x1 = tf32r(x1); x2 = tf32r(x2); x3 = tf32r(x3); }
                a[mt][0] = __float_as_uint(x0);
                a[mt][1] = __float_as_uint(x1);
                a[mt][2] = __float_as_uint(x2);
                a[mt][3] = __float_as_uint(x3);
            }
#pragma unroll
            for (int nt = 0; nt < 8; nt++) {
                const int nc = n0 + nt * 8 + g;
                float y0 = Bs[(kk + tig)     * GLDB + nc];
                float y1 = Bs[(kk + tig + 4) * GLDB + nc];
                if (RB) { y0 = tf32r(y0); y1 = tf32r(y1); }
                const uint32_t b0 = __float_as_uint(y0);
                const uint32_t b1 = __float_as_uint(y1);
                mma_tf32(acc[0][nt], a[0][0], a[0][1], a[0][2], a[0][3], b0, b1);
                mma_tf32(acc[1][nt], a[1][0], a[1][1], a[1][2], a[1][3], b0, b1);
            }
        }
    }

    // epilogue
#pragma unroll
    for (int mt = 0; mt < 2; mt++) {
        const int r = m0 + mt * 16;
#pragma unroll
        for (int nt = 0; nt < 8; nt++) {
            const int col = n0 + nt * 8 + tig * 2;
            const float b0 = bias[col], b1 = bias[col + 1];
            float2 o0, o1;
            o0.x = (acc[mt][nt][0] + b0) * mul;  o0.y = (acc[mt][nt][1] + b1) * mul;
            o1.x = (acc[mt][nt][2] + b0) * mul;  o1.y = (acc[mt][nt][3] + b1) * mul;
            if (round_out) {
                o0.x = tf32r(o0.x); o0.y = tf32r(o0.y);
                o1.x = tf32r(o1.x); o1.y = tf32r(o1.y);
            }
            *(float2*)&C[(size_t)(r + g)     * ldc + col] = o0;
            *(float2*)&C[(size_t)(r + g + 8) * ldc + col] = o1;
        }
    }
}

// ---------------------------------------------------------------------------
// Kernel 1: fused QKV projection.  grid (16 Mtiles, 8 views, 3 proj)
// ---------------------------------------------------------------------------
__global__ void __launch_bounds__(256, 2) proj_kernel(
    const float* __restrict__ q, const float* __restrict__ k,
    const float* __restrict__ v,
    const float* __restrict__ wq, const float* __restrict__ bq,
    const float* __restrict__ wk, const float* __restrict__ bk,
    const float* __restrict__ wv, const float* __restrict__ bv)
{
    const int view = blockIdx.y;
    const int pz   = blockIdx.z;
    const float *A, *W, *bias;
    float* O;
    float mul = 1.0f;
    if (pz == 0)      { A = q; W = wq; bias = bq; O = g_qh; mul = SCALE; }
    else if (pz == 1) { A = k; W = wk; bias = bk; O = g_kh; }
    else              { A = v; W = wv; bias = bv; O = g_vh; }

    A += (size_t)view * SEQL * HID;
    O += (size_t)view * SEQL * ATT;
    const int row0 = blockIdx.x * 128;
    sgemm_pipe<true, true>(A + (size_t)row0 * HID, HID, W, ATT, bias,
                           O + (size_t)row0 * ATT, ATT, HID, mul, true);
}

// ---------------------------------------------------------------------------
// Kernel 1b: bias GEMM.  g_x[q][v*A+a] = attn_bias[v,q,:] @ vh[v,:,a]
// grid (16 Mtiles, 8 views).  B (g_vh) is pre-rounded -> no cvt.
// ---------------------------------------------------------------------------
__global__ void __launch_bounds__(256, 2) biasv_kernel(const float* __restrict__ attn_bias)
{
    const int view = blockIdx.y;
    const int row0 = blockIdx.x * 128;
    const float* A = attn_bias + (size_t)view * SEQL * SEQL + (size_t)row0 * SEQL;
    const float* B = g_vh + (size_t)view * SEQL * ATT;
    float* C = g_x + (size_t)row0 * HID + view * ATT;
    sgemm_pipe<true, false>(A, SEQL, B, ATT, g_zero, C, HID, SEQL, 1.0f, false);
}

// ---------------------------------------------------------------------------
// Kernel 2: FA2-style attention, register softmax + REGISTER-RESIDENT Q frags,
//   128 threads (4 warps), BQ=64, BK=32, double-buffered cp.async K/V.
//   grid (32 q-tiles, 8 views) = 256 CTAs, 2/SM (smem 100KB).
//   Epilogue adds into g_x (holds bias@V term from biasv_kernel).
// ---------------------------------------------------------------------------
#define BQ    64
#define BK    32
#define NT_KT (SEQL / BK)    // 64
#define LDQ   132
#define LDV   136
#define KSTG  (BK * LDQ)
#define VSTG  (BK * LDV)
#define SMEM_ATTN_FLOATS (BQ * LDQ + 2 * KSTG + 2 * VSTG)
#define SMEM_ATTN_BYTES  (SMEM_ATTN_FLOATS * 4)

__global__ void __launch_bounds__(128) attn_kernel()
{
    extern __shared__ float sm[];
    float* Qs = sm;
    float* Kb = Qs + BQ * LDQ;
    float* Vb = Kb + 2 * KSTG;

    const int tid  = threadIdx.x;
    const int wid  = tid >> 5;
    const int lane = tid & 31;
    const int g    = lane >> 2;
    const int tig  = lane & 3;

    const int view = blockIdx.y;
    const int q0   = blockIdx.x * BQ;

    const float* qh = g_qh + (size_t)view * SEQL * ATT + (size_t)q0 * ATT;
    const float* kh = g_kh + (size_t)view * SEQL * ATT;
    const float* vh = g_vh + (size_t)view * SEQL * ATT;

    const uint32_t sQ = smem_u32(Qs);
    const uint32_t sK = smem_u32(Kb);
    const uint32_t sV = smem_u32(Vb);

    auto issueKV = [&](int it) {
        const int buf = it & 1;
        const float* kbase = kh + (size_t)(it * BK) * ATT;
        const float* vbase = vh + (size_t)(it * BK) * ATT;
#pragma unroll
        for (int i = 0; i < 8; i++) {
            const int idx = tid + i * 128;
            const int r = idx >> 5, c4 = (idx & 31) << 2;
            cpasync16(sK + (uint32_t)(buf * KSTG + r * LDQ + c4) * 4,
                      &kbase[(size_t)r * ATT + c4]);
            cpasync16(sV + (uint32_t)(buf * VSTG + r * LDV + c4) * 4,
                      &vbase[(size_t)r * ATT + c4]);
        }
        CP_COMMIT();
    };

    // prologue: group0 = Q + KV(0); group1 = KV(1)
    {
#pragma unroll
        for (int i = 0; i < 16; i++) {
            const int idx = tid + i * 128;
            const int r = idx >> 5, c4 = (idx & 31) << 2;
            cpasync16(sQ + (uint32_t)(r * LDQ + c4) * 4, &qh[(size_t)r * ATT + c4]);
        }
#pragma unroll
        for (int i = 0; i < 8; i++) {
            const int idx = tid + i * 128;
            const int r = idx >> 5, c4 = (idx & 31) << 2;
            cpasync16(sK + (uint32_t)(r * LDQ + c4) * 4, &kh[(size_t)r * ATT + c4]);
            cpasync16(sV + (uint32_t)(r * LDV + c4) * 4, &vh[(size_t)r * ATT + c4]);
        }
        CP_COMMIT();
        issueKV(1);
    }

    const int m0 = wid * 16;

    // ---- hoist Q fragments to registers (Q invariant across kt loop) ----
    uint32_t qf[16][4];
    CP_WAIT1();               // group0 (Q + KV0) complete
    __syncthreads();
#pragma unroll
    for (int s = 0; s < 16; s++) {
        const int kk = s * 8;
        qf[s][0] = lduf(&Qs[(m0 + g)     * LDQ + kk + tig]);
        qf[s][1] = lduf(&Qs[(m0 + g + 8) * LDQ + kk + tig]);
        qf[s][2] = lduf(&Qs[(m0 + g)     * LDQ + kk + tig + 4]);
        qf[s][3] = lduf(&Qs[(m0 + g + 8) * LDQ + kk + tig + 4]);
    }

    float oacc[16][4];
#pragma unroll
    for (int nt = 0; nt < 16; nt++)
#pragma unroll
        for (int i = 0; i < 4; i++) oacc[nt][i] = 0.f;

    float mst0 = -3.0e38f, mst1 = -3.0e38f;
    float lst0 = 0.f,      lst1 = 0.f;

    const int srcA = (g << 2) + (tig >> 1);
    const int srcB = srcA + 2;
    const bool odd = (tig & 1);

    for (int kt = 0; kt < NT_KT; kt++) {
        if (kt + 1 < NT_KT) CP_WAIT1(); else CP_WAIT0();
        __syncthreads();

        const float* Ks = Kb + (kt & 1) * KSTG;
        const float* Vs = Vb + (kt & 1) * VSTG;

        // ---- phase 1: S(16x32 per warp) = Q @ K^T ----
        float sacc[4][4];
#pragma unroll
        for (int j = 0; j < 4; j++)
#pragma unroll
            for (int i = 0; i < 4; i++) sacc[j][i] = 0.f;

#pragma unroll
        for (int s = 0; s < 16; s++) {
            const int kk = s * 8;
#pragma unroll
            for (int j = 0; j < 4; j++) {
                const int nr = j * 8 + g;
                const uint32_t b0 = lduf(&Ks[nr * LDQ + kk + tig]);
                const uint32_t b1 = lduf(&Ks[nr * LDQ + kk + tig + 4]);
                mma_tf32(sacc[j], qf[s][0], qf[s][1], qf[s][2], qf[s][3], b0, b1);
            }
        }

        // ---- phase 2: register online softmax ----
        {
            float mx0 = -3.0e38f, mx1 = -3.0e38f;
#pragma unroll
            for (int j = 0; j < 4; j++) {
                mx0 = fmaxf(mx0, fmaxf(sacc[j][0], sacc[j][1]));
                mx1 = fmaxf(mx1, fmaxf(sacc[j][2], sacc[j][3]));
            }
            mx0 = fmaxf(mx0, __shfl_xor_sync(0xffffffffu, mx0, 1));
            mx0 = fmaxf(mx0, __shfl_xor_sync(0xffffffffu, mx0, 2));
            mx1 = fmaxf(mx1, __shfl_xor_sync(0xffffffffu, mx1, 1));
            mx1 = fmaxf(mx1, __shfl_xor_sync(0xffffffffu, mx1, 2));

            const float mnew0 = fmaxf(mst0, mx0);
            const float mnew1 = fmaxf(mst1, mx1);
            const float corr0 = __expf(mst0 - mnew0);
            const float corr1 = __expf(mst1 - mnew1);
            mst0 = mnew0; mst1 = mnew1;

            float s0 = 0.f, s1 = 0.f;
#pragma unroll
            for (int j = 0; j < 4; j++) {
                float e;
                e = __expf(sacc[j][0] - mnew0); s0 += e; sacc[j][0] = tf32r(e);
                e = __expf(sacc[j][1] - mnew0); s0 += e; sacc[j][1] = tf32r(e);
                e = __expf(sacc[j][2] - mnew1); s1 += e; sacc[j][2] = tf32r(e);
                e = __expf(sacc[j][3] - mnew1); s1 += e; sacc[j][3] = tf32r(e);
            }
            s0 += __shfl_xor_sync(0xffffffffu, s0, 1);
            s0 += __shfl_xor_sync(0xffffffffu, s0, 2);
            s1 += __shfl_xor_sync(0xffffffffu, s1, 1);
            s1 += __shfl_xor_sync(0xffffffffu, s1, 2);
            lst0 = lst0 * corr0 + s0;
            lst1 = lst1 * corr1 + s1;

#pragma unroll
            for (int nt = 0; nt < 16; nt++) {
                oacc[nt][0] *= corr0; oacc[nt][1] *= corr0;
                oacc[nt][2] *= corr1; oacc[nt][3] *= corr1;
            }
        }

        // ---- phase 3: oacc += P @ V  (register shfl transpose) ----
#pragma unroll
        for (int jk = 0; jk < 4; jk++) {
            const float e0 = __shfl_sync(0xffffffffu, sacc[jk][0], srcA);
            const float e1 = __shfl_sync(0xffffffffu, sacc[jk][1], srcA);
            const float f0 = __shfl_sync(0xffffffffu, sacc[jk][2], srcA);
            const float f1 = __shfl_sync(0xffffffffu, sacc[jk][3], srcA);
            const float e2 = __shfl_sync(0xffffffffu, sacc[jk][0], srcB);
            const float e3 = __shfl_sync(0xffffffffu, sacc[jk][1], srcB);
            const float f2 = __shfl_sync(0xffffffffu, sacc[jk][2], srcB);
            const float f3 = __shfl_sync(0xffffffffu, sacc[jk][3], srcB);
            const uint32_t a0 = __float_as_uint(odd ? e1 : e0);
            const uint32_t a1 = __float_as_uint(odd ? f1 : f0);
            const uint32_t a2 = __float_as_uint(odd ? e3 : e2);
            const uint32_t a3 = __float_as_uint(odd ? f3 : f2);
#pragma unroll
            for (int nt = 0; nt < 16; nt++) {
                const int nc = nt * 8 + g;
                const uint32_t b0 = lduf(&Vs[(jk * 8 + tig)     * LDV + nc]);
                const uint32_t b1 = lduf(&Vs[(jk * 8 + tig + 4) * LDV + nc]);
                mma_tf32(oacc[nt], a0, a1, a2, a3, b0, b1);
            }
        }

        __syncthreads();
        if (kt + 2 < NT_KT) issueKV(kt + 2);
    }

    // ---- epilogue: g_x += oacc / l  (g_x holds bias@V term) ----
    const float inv0 = 1.f / lst0;
    const float inv1 = 1.f / lst1;
    float* xr0 = g_x + (size_t)(q0 + m0 + g)     * HID + view * ATT;
    float* xr1 = g_x + (size_t)(q0 + m0 + g + 8) * HID + view * ATT;
#pragma unroll
    for (int nt = 0; nt < 16; nt++) {
        const int col = nt * 8 + tig * 2;
        float2 x0 = *(const float2*)&xr0[col];
        float2 x1 = *(const float2*)&xr1[col];
        x0.x += oacc[nt][0] * inv0;  x0.y += oacc[nt][1] * inv0;
        x1.x += oacc[nt][2] * inv1;  x1.y += oacc[nt][3] * inv1;
        *(float2*)&xr0[col] = x0;
        *(float2*)&xr1[col] = x1;
    }
}

// ---------------------------------------------------------------------------
// Kernel 3: out = x @ wo + bo.   grid (16 Mtiles, 8 Ntiles)
// ---------------------------------------------------------------------------
__global__ void __launch_bounds__(256, 2) out_kernel(
    const float* __restrict__ wo, const float* __restrict__ bo,
    float* __restrict__ out)
{
    const int row0 = blockIdx.x * 128;
    const int col0 = blockIdx.y * 128;
    sgemm_pipe<true, true>(g_x + (size_t)row0 * HID, HID,
                           wo + col0, HID, bo + col0,
                           out + (size_t)row0 * HID + col0, HID, HID, 1.0f, false);
}

// ---------------------------------------------------------------------------
extern "C" void kernel_launch(void* const* d_in, const int* in_sizes, int n_in,
                              void* d_out, int out_size)
{
    const float* q  = (const float*)d_in[0];
    const float* k  = (const float*)d_in[1];
    const float* v  = (const float*)d_in[2];
    const float* ab = (const float*)d_in[3];
    const float* wq = (const float*)d_in[4];
    const float* bq = (const float*)d_in[5];
    const float* wk = (const float*)d_in[6];
    const float* bk = (const float*)d_in[7];
    const float* wv = (const float*)d_in[8];
    const float* bv = (const float*)d_in[9];
    const float* wo = (const float*)d_in[10];
    const float* bo = (const float*)d_in[11];
    float* out = (float*)d_out;

    cudaFuncSetAttribute(proj_kernel,  cudaFuncAttributeMaxDynamicSharedMemorySize, SMEM_GEMM_BYTES);
    cudaFuncSetAttribute(biasv_kernel, cudaFuncAttributeMaxDynamicSharedMemorySize, SMEM_GEMM_BYTES);
    cudaFuncSetAttribute(out_kernel,   cudaFuncAttributeMaxDynamicSharedMemorySize, SMEM_GEMM_BYTES);
    cudaFuncSetAttribute(attn_kernel,  cudaFuncAttributeMaxDynamicSharedMemorySize, SMEM_ATTN_BYTES);

    proj_kernel<<<dim3(SEQL / 128, VIEWS, 3), 256, SMEM_GEMM_BYTES>>>(
        q, k, v, wq, bq, wk, bk, wv, bv);
    biasv_kernel<<<dim3(SEQL / 128, VIEWS), 256, SMEM_GEMM_BYTES>>>(ab);
    attn_kernel<<<dim3(SEQL / BQ, VIEWS), 128, SMEM_ATTN_BYTES>>>();
    out_kernel<<<dim3(SEQL / 128, HID / 128), 256, SMEM_GEMM_BYTES>>>(wo, bo, out);
}

// round 14
// speedup vs baseline: 1.1111x; 1.0980x over previous
#include <cuda_runtime.h>
#include <math.h>
#include <stdint.h>

#define VIEWS 8
#define SEQL  2048
#define HID   1024
#define ATT   128
#define SCALE 0.08838834764831845f   /* 1/sqrt(128) */

// ---------------- scratch (device globals: no allocations allowed) ----------
__device__ float g_qh[VIEWS * SEQL * ATT];   // tf32-rounded
__device__ float g_kh[VIEWS * SEQL * ATT];   // tf32-rounded
__device__ float g_vh[VIEWS * SEQL * ATT];   // tf32-rounded
__device__ float g_x [SEQL * HID];           // bias@V partial 0; then final x
__device__ float g_x2[SEQL * HID];           // bias@V partial 1; then out partial 1
__device__ float g_tmp[SEQL * HID];          // out partial 0
__device__ float g_zero[ATT];                // zero bias

// ---------------------------------------------------------------------------
// helpers
// ---------------------------------------------------------------------------
__device__ __forceinline__ float tf32r(float x) {
    uint32_t u;
    asm("cvt.rna.tf32.f32 %0, %1;" : "=r"(u) : "f"(x));
    return __uint_as_float(u);
}

__device__ __forceinline__ void mma_tf32(float* d,
    uint32_t a0, uint32_t a1, uint32_t a2, uint32_t a3,
    uint32_t b0, uint32_t b1)
{
    asm volatile(
        "mma.sync.aligned.m16n8k8.row.col.f32.tf32.tf32.f32 "
        "{%0,%1,%2,%3},{%4,%5,%6,%7},{%8,%9},{%0,%1,%2,%3};\n"
        : "+f"(d[0]), "+f"(d[1]), "+f"(d[2]), "+f"(d[3])
        : "r"(a0), "r"(a1), "r"(a2), "r"(a3), "r"(b0), "r"(b1));
}

__device__ __forceinline__ uint32_t lduf(const float* p) {
    return __float_as_uint(*p);
}
__device__ __forceinline__ uint32_t smem_u32(const void* p) {
    uint32_t a;
    asm("{ .reg .u64 t; cvta.to.shared.u64 t, %1; cvt.u32.u64 %0, t; }"
        : "=r"(a) : "l"(p));
    return a;
}
__device__ __forceinline__ void cpasync16(uint32_t dst, const void* src) {
    asm volatile("cp.async.cg.shared.global [%0], [%1], 16;\n" :: "r"(dst), "l"(src));
}
#define CP_COMMIT() asm volatile("cp.async.commit_group;\n" ::: "memory")
#define CP_WAIT0()  asm volatile("cp.async.wait_group 0;\n"  ::: "memory")
#define CP_WAIT1()  asm volatile("cp.async.wait_group 1;\n"  ::: "memory")

// ============================================================================
// TF32 tensor-core GEMM, 128x128 block, 256 threads (8 warps, 4m x 2n),
// warp tile 32x64, BK=32, 3-stage cp.async smem pipeline.  (R10 config)
// C = (A@B + bias) * mul.  TF32 rounding at fragment load when needed.
// ============================================================================
#define GLDA 36     // As row stride (pad)
#define GLDB 136    // Bs row stride (pad)
#define STG_F (128 * GLDA + 32 * GLDB)          // floats per stage = 8960
#define SMEM_GEMM_BYTES (3 * STG_F * 4)         // 107520 B

template<bool RA, bool RB>
__device__ __forceinline__ void sgemm_pipe(
    const float* __restrict__ A, int lda,
    const float* __restrict__ B, int ldb,
    const float* __restrict__ bias,
    float* __restrict__ C, int ldc,
    int Ktot, float mul, bool round_out)
{
    extern __shared__ float dynsm[];

    const int tid  = threadIdx.x;
    const int wid  = tid >> 5;
    const int lane = tid & 31;
    const int g    = lane >> 2;
    const int tig  = lane & 3;

    const int m0 = (wid & 3) * 32;
    const int n0 = (wid >> 2) * 64;

    const int ar  = tid >> 3, ac4 = (tid & 7) << 2;
    const int br  = tid >> 5, bc4 = (tid & 31) << 2;

    const int niter = Ktot >> 5;

    auto issue = [&](int it) {
        const int k0 = it << 5;
        float* As = dynsm + (it % 3) * STG_F;
        float* Bs = As + 128 * GLDA;
        const uint32_t sA = smem_u32(As), sB = smem_u32(Bs);
#pragma unroll
        for (int i = 0; i < 4; i++) {
            const int r  = ar + i * 32;
            cpasync16(sA + (uint32_t)(r * GLDA + ac4) * 4,
                      &A[(size_t)r * lda + k0 + ac4]);
            const int rb = br + i * 8;
            cpasync16(sB + (uint32_t)(rb * GLDB + bc4) * 4,
                      &B[(size_t)(k0 + rb) * ldb + bc4]);
        }
        CP_COMMIT();
    };

    float acc[2][8][4];
#pragma unroll
    for (int mt = 0; mt < 2; mt++)
#pragma unroll
        for (int nt = 0; nt < 8; nt++)
#pragma unroll
            for (int i = 0; i < 4; i++) acc[mt][nt][i] = 0.f;

    issue(0);
    if (niter > 1) issue(1);

    for (int it = 0; it < niter; it++) {
        if (it + 1 < niter) CP_WAIT1(); else CP_WAIT0();
        __syncthreads();
        if (it + 2 < niter) issue(it + 2);

        const float* As = dynsm + (it % 3) * STG_F;
        const float* Bs = As + 128 * GLDA;

#pragma unroll
        for (int kk = 0; kk < 32; kk += 8) {
            uint32_t a[2][4];
#pragma unroll
            for (int mt = 0; mt < 2; mt++) {
                const int r = m0 + mt * 16;
                float x0 = As[(r + g)     * GLDA + kk + tig];
                float x1 = As[(r + g + 8) * GLDA + kk + tig];
                float x2 = As[(r + g)     * GLDA + kk + tig + 4];
                float x3 = As[(r + g + 8) * GLDA + kk + tig + 4];
                if (RA) { x0 = tf32r(x0); x1 = tf32r(x1); x2 = tf32r(x2); x3 = tf32r(x3); }
                a[mt][0] = __float_as_uint(x0);
                a[mt][1] = __float_as_uint(x1);
                a[mt][2] = __float_as_uint(x2);
                a[mt][3] = __float_as_uint(x3);
            }
#pragma unroll
            for (int nt = 0; nt < 8; nt++) {
                const int nc = n0 + nt * 8 + g;
                float y0 = Bs[(kk + tig)     * GLDB + nc];
                float y1 = Bs[(kk + tig + 4) * GLDB + nc];
                if (RB) { y0 = tf32r(y0); y1 = tf32r(y1); }
                const uint32_t b0 = __float_as_uint(y0);
                const uint32_t b1 = __float_as_uint(y1);
                mma_tf32(acc[0][nt], a[0][0], a[0][1], a[0][2], a[0][3], b0, b1);
                mma_tf32(acc[1][nt], a[1][0], a[1][1], a[1][2], a[1][3], b0, b1);
            }
        }
    }

    // epilogue
#pragma unroll
    for (int mt = 0; mt < 2; mt++) {
        const int r = m0 + mt * 16;
#pragma unroll
        for (int nt = 0; nt < 8; nt++) {
            const int col = n0 + nt * 8 + tig * 2;
            const float b0 = bias[col], b1 = bias[col + 1];
            float2 o0, o1;
            o0.x = (acc[mt][nt][0] + b0) * mul;  o0.y = (acc[mt][nt][1] + b1) * mul;
            o1.x = (acc[mt][nt][2] + b0) * mul;  o1.y = (acc[mt][nt][3] + b1) * mul;
            if (round_out) {
                o0.x = tf32r(o0.x); o0.y = tf32r(o0.y);
                o1.x = tf32r(o1.x); o1.y = tf32r(o1.y);
            }
            *(float2*)&C[(size_t)(r + g)     * ldc + col] = o0;
            *(float2*)&C[(size_t)(r + g + 8) * ldc + col] = o1;
        }
    }
}

// ---------------------------------------------------------------------------
// Kernel 1: fused QKV projection.  grid (16 Mtiles, 8 views, 3 proj)
// ---------------------------------------------------------------------------
__global__ void __launch_bounds__(256, 2) proj_kernel(
    const float* __restrict__ q, const float* __restrict__ k,
    const float* __restrict__ v,
    const float* __restrict__ wq, const float* __restrict__ bq,
    const float* __restrict__ wk, const float* __restrict__ bk,
    const float* __restrict__ wv, const float* __restrict__ bv)
{
    const int view = blockIdx.y;
    const int pz   = blockIdx.z;
    const float *A, *W, *bias;
    float* O;
    float mul = 1.0f;
    if (pz == 0)      { A = q; W = wq; bias = bq; O = g_qh; mul = SCALE; }
    else if (pz == 1) { A = k; W = wk; bias = bk; O = g_kh; }
    else              { A = v; W = wv; bias = bv; O = g_vh; }

    A += (size_t)view * SEQL * HID;
    O += (size_t)view * SEQL * ATT;
    const int row0 = blockIdx.x * 128;
    sgemm_pipe<true, true>(A + (size_t)row0 * HID, HID, W, ATT, bias,
                           O + (size_t)row0 * ATT, ATT, HID, mul, true);
}

// ---------------------------------------------------------------------------
// Kernel 1b: bias GEMM, K-split x2.  grid (16 Mtiles, 8 views, 2 ksplit).
//   half h: partial over K in [h*1024, h*1024+1024)  ->  g_x / g_x2
// ---------------------------------------------------------------------------
__global__ void __launch_bounds__(256, 2) biasv_kernel(const float* __restrict__ attn_bias)
{
    const int view = blockIdx.y;
    const int row0 = blockIdx.x * 128;
    const int h    = blockIdx.z;
    const int k0   = h * (SEQL / 2);
    const float* A = attn_bias + (size_t)view * SEQL * SEQL + (size_t)row0 * SEQL + k0;
    const float* B = g_vh + (size_t)view * SEQL * ATT + (size_t)k0 * ATT;
    float* C = (h == 0 ? g_x : g_x2) + (size_t)row0 * HID + view * ATT;
    sgemm_pipe<true, false>(A, SEQL, B, ATT, g_zero, C, HID, SEQL / 2, 1.0f, false);
}

// ---------------------------------------------------------------------------
// Kernel 2: FA2-style attention (exact R10 form), 128 threads (4 warps),
//   BQ=64, BK=32, double-buffered cp.async K/V, grid (32, 8) = 256 CTAs.
//   Epilogue: g_x = g_x + g_x2 + oacc/l   (partials from biasv halves).
// ---------------------------------------------------------------------------
#define BQ    64
#define BK    32
#define NT_KT (SEQL / BK)    // 64
#define LDQ   132
#define LDV   136
#define KSTG  (BK * LDQ)
#define VSTG  (BK * LDV)
#define SMEM_ATTN_FLOATS (BQ * LDQ + 2 * KSTG + 2 * VSTG)
#define SMEM_ATTN_BYTES  (SMEM_ATTN_FLOATS * 4)

__global__ void __launch_bounds__(128) attn_kernel()
{
    extern __shared__ float sm[];
    float* Qs = sm;
    float* Kb = Qs + BQ * LDQ;
    float* Vb = Kb + 2 * KSTG;

    const int tid  = threadIdx.x;
    const int wid  = tid >> 5;
    const int lane = tid & 31;
    const int g    = lane >> 2;
    const int tig  = lane & 3;

    const int view = blockIdx.y;
    const int q0   = blockIdx.x * BQ;

    const float* qh = g_qh + (size_t)view * SEQL * ATT + (size_t)q0 * ATT;
    const float* kh = g_kh + (size_t)view * SEQL * ATT;
    const float* vh = g_vh + (size_t)view * SEQL * ATT;

    const uint32_t sQ = smem_u32(Qs);
    const uint32_t sK = smem_u32(Kb);
    const uint32_t sV = smem_u32(Vb);

    auto issueKV = [&](int it) {
        const int buf = it & 1;
        const float* kbase = kh + (size_t)(it * BK) * ATT;
        const float* vbase = vh + (size_t)(it * BK) * ATT;
#pragma unroll
        for (int i = 0; i < 8; i++) {
            const int idx = tid + i * 128;
            const int r = idx >> 5, c4 = (idx & 31) << 2;
            cpasync16(sK + (uint32_t)(buf * KSTG + r * LDQ + c4) * 4,
                      &kbase[(size_t)r * ATT + c4]);
            cpasync16(sV + (uint32_t)(buf * VSTG + r * LDV + c4) * 4,
                      &vbase[(size_t)r * ATT + c4]);
        }
        CP_COMMIT();
    };

    // prologue: group0 = Q + KV(0); group1 = KV(1)
    {
#pragma unroll
        for (int i = 0; i < 16; i++) {
            const int idx = tid + i * 128;
            const int r = idx >> 5, c4 = (idx & 31) << 2;
            cpasync16(sQ + (uint32_t)(r * LDQ + c4) * 4, &qh[(size_t)r * ATT + c4]);
        }
#pragma unroll
        for (int i = 0; i < 8; i++) {
            const int idx = tid + i * 128;
            const int r = idx >> 5, c4 = (idx & 31) << 2;
            cpasync16(sK + (uint32_t)(r * LDQ + c4) * 4, &kh[(size_t)r * ATT + c4]);
            cpasync16(sV + (uint32_t)(r * LDV + c4) * 4, &vh[(size_t)r * ATT + c4]);
        }
        CP_COMMIT();
        issueKV(1);
    }

    const int m0 = wid * 16;

    float oacc[16][4];
#pragma unroll
    for (int nt = 0; nt < 16; nt++)
#pragma unroll
        for (int i = 0; i < 4; i++) oacc[nt][i] = 0.f;

    float mst0 = -3.0e38f, mst1 = -3.0e38f;
    float lst0 = 0.f,      lst1 = 0.f;

    const int srcA = (g << 2) + (tig >> 1);
    const int srcB = srcA + 2;
    const bool odd = (tig & 1);

    for (int kt = 0; kt < NT_KT; kt++) {
        if (kt + 1 < NT_KT) CP_WAIT1(); else CP_WAIT0();
        __syncthreads();

        const float* Ks = Kb + (kt & 1) * KSTG;
        const float* Vs = Vb + (kt & 1) * VSTG;

        // ---- phase 1: S(16x32 per warp) = Q @ K^T ----
        float sacc[4][4];
#pragma unroll
        for (int j = 0; j < 4; j++)
#pragma unroll
            for (int i = 0; i < 4; i++) sacc[j][i] = 0.f;

#pragma unroll
        for (int kk = 0; kk < ATT; kk += 8) {
            const uint32_t a0 = lduf(&Qs[(m0 + g)     * LDQ + kk + tig]);
            const uint32_t a1 = lduf(&Qs[(m0 + g + 8) * LDQ + kk + tig]);
            const uint32_t a2 = lduf(&Qs[(m0 + g)     * LDQ + kk + tig + 4]);
            const uint32_t a3 = lduf(&Qs[(m0 + g + 8) * LDQ + kk + tig + 4]);
#pragma unroll
            for (int j = 0; j < 4; j++) {
                const int nr = j * 8 + g;
                const uint32_t b0 = lduf(&Ks[nr * LDQ + kk + tig]);
                const uint32_t b1 = lduf(&Ks[nr * LDQ + kk + tig + 4]);
                mma_tf32(sacc[j], a0, a1, a2, a3, b0, b1);
            }
        }

        // ---- phase 2: register online softmax ----
        {
            float mx0 = -3.0e38f, mx1 = -3.0e38f;
#pragma unroll
            for (int j = 0; j < 4; j++) {
                mx0 = fmaxf(mx0, fmaxf(sacc[j][0], sacc[j][1]));
                mx1 = fmaxf(mx1, fmaxf(sacc[j][2], sacc[j][3]));
            }
            mx0 = fmaxf(mx0, __shfl_xor_sync(0xffffffffu, mx0, 1));
            mx0 = fmaxf(mx0, __shfl_xor_sync(0xffffffffu, mx0, 2));
            mx1 = fmaxf(mx1, __shfl_xor_sync(0xffffffffu, mx1, 1));
            mx1 = fmaxf(mx1, __shfl_xor_sync(0xffffffffu, mx1, 2));

            const float mnew0 = fmaxf(mst0, mx0);
            const float mnew1 = fmaxf(mst1, mx1);
            const float corr0 = __expf(mst0 - mnew0);
            const float corr1 = __expf(mst1 - mnew1);
            mst0 = mnew0; mst1 = mnew1;

            float s0 = 0.f, s1 = 0.f;
#pragma unroll
            for (int j = 0; j < 4; j++) {
                float e;
                e = __expf(sacc[j][0] - mnew0); s0 += e; sacc[j][0] = tf32r(e);
                e = __expf(sacc[j][1] - mnew0); s0 += e; sacc[j][1] = tf32r(e);
                e = __expf(sacc[j][2] - mnew1); s1 += e; sacc[j][2] = tf32r(e);
                e = __expf(sacc[j][3] - mnew1); s1 += e; sacc[j][3] = tf32r(e);
            }
            s0 += __shfl_xor_sync(0xffffffffu, s0, 1);
            s0 += __shfl_xor_sync(0xffffffffu, s0, 2);
            s1 += __shfl_xor_sync(0xffffffffu, s1, 1);
            s1 += __shfl_xor_sync(0xffffffffu, s1, 2);
            lst0 = lst0 * corr0 + s0;
            lst1 = lst1 * corr1 + s1;

#pragma unroll
            for (int nt = 0; nt < 16; nt++) {
                oacc[nt][0] *= corr0; oacc[nt][1] *= corr0;
                oacc[nt][2] *= corr1; oacc[nt][3] *= corr1;
            }
        }

        // ---- phase 3: oacc += P @ V  (register shfl transpose) ----
#pragma unroll
        for (int jk = 0; jk < 4; jk++) {
            const float e0 = __shfl_sync(0xffffffffu, sacc[jk][0], srcA);
            const float e1 = __shfl_sync(0xffffffffu, sacc[jk][1], srcA);
            const float f0 = __shfl_sync(0xffffffffu, sacc[jk][2], srcA);
            const float f1 = __shfl_sync(0xffffffffu, sacc[jk][3], srcA);
            const float e2 = __shfl_sync(0xffffffffu, sacc[jk][0], srcB);
            const float e3 = __shfl_sync(0xffffffffu, sacc[jk][1], srcB);
            const float f2 = __shfl_sync(0xffffffffu, sacc[jk][2], srcB);
            const float f3 = __shfl_sync(0xffffffffu, sacc[jk][3], srcB);
            const uint32_t a0 = __float_as_uint(odd ? e1 : e0);
            const uint32_t a1 = __float_as_uint(odd ? f1 : f0);
            const uint32_t a2 = __float_as_uint(odd ? e3 : e2);
            const uint32_t a3 = __float_as_uint(odd ? f3 : f2);
#pragma unroll
            for (int nt = 0; nt < 16; nt++) {
                const int nc = nt * 8 + g;
                const uint32_t b0 = lduf(&Vs[(jk * 8 + tig)     * LDV + nc]);
                const uint32_t b1 = lduf(&Vs[(jk * 8 + tig + 4) * LDV + nc]);
                mma_tf32(oacc[nt], a0, a1, a2, a3, b0, b1);
            }
        }

        __syncthreads();
        if (kt + 2 < NT_KT) issueKV(kt + 2);
    }

    // ---- epilogue: g_x = g_x + g_x2 + oacc / l ----
    const float inv0 = 1.f / lst0;
    const float inv1 = 1.f / lst1;
    const size_t off0 = (size_t)(q0 + m0 + g)     * HID + view * ATT;
    const size_t off1 = (size_t)(q0 + m0 + g + 8) * HID + view * ATT;
#pragma unroll
    for (int nt = 0; nt < 16; nt++) {
        const int col = nt * 8 + tig * 2;
        float2 x0 = *(const float2*)&g_x [off0 + col];
        float2 y0 = *(const float2*)&g_x2[off0 + col];
        float2 x1 = *(const float2*)&g_x [off1 + col];
        float2 y1 = *(const float2*)&g_x2[off1 + col];
        x0.x += y0.x + oacc[nt][0] * inv0;  x0.y += y0.y + oacc[nt][1] * inv0;
        x1.x += y1.x + oacc[nt][2] * inv1;  x1.y += y1.y + oacc[nt][3] * inv1;
        *(float2*)&g_x[off0 + col] = x0;
        *(float2*)&g_x[off1 + col] = x1;
    }
}

// ---------------------------------------------------------------------------
// Kernel 3: out partials, K-split x2.  grid (16 Mtiles, 8 Ntiles, 2 ksplit).
//   half h: partial over K in [h*512, h*512+512)  ->  g_tmp / g_x2
// ---------------------------------------------------------------------------
__global__ void __launch_bounds__(256, 2) out_kernel(
    const float* __restrict__ wo)
{
    const int row0 = blockIdx.x * 128;
    const int col0 = blockIdx.y * 128;
    const int h    = blockIdx.z;
    const int k0   = h * (HID / 2);
    float* C = (h == 0 ? g_tmp : g_x2) + (size_t)row0 * HID + col0;
    sgemm_pipe<true, true>(g_x + (size_t)row0 * HID + k0, HID,
                           wo + (size_t)k0 * HID + col0, HID, g_zero,
                           C, HID, HID / 2, 1.0f, false);
}

// ---------------------------------------------------------------------------
// Kernel 3b: out = t0 + t1 + bo.  grid 2048, 256 threads, float4.
// ---------------------------------------------------------------------------
__global__ void __launch_bounds__(256) combine_kernel(
    const float* __restrict__ bo, float* __restrict__ out)
{
    const int idx = blockIdx.x * 256 + threadIdx.x;      // float4 index
    const int c4  = (idx & (HID / 4 - 1)) * 4;
    const float4 t0 = *(const float4*)&g_tmp[(size_t)idx * 4];
    const float4 t1 = *(const float4*)&g_x2 [(size_t)idx * 4];
    const float4 bb = *(const float4*)&bo[c4];
    float4 o;
    o.x = t0.x + t1.x + bb.x;
    o.y = t0.y + t1.y + bb.y;
    o.z = t0.z + t1.z + bb.z;
    o.w = t0.w + t1.w + bb.w;
    *(float4*)&out[(size_t)idx * 4] = o;
}

// ---------------------------------------------------------------------------
extern "C" void kernel_launch(void* const* d_in, const int* in_sizes, int n_in,
                              void* d_out, int out_size)
{
    const float* q  = (const float*)d_in[0];
    const float* k  = (const float*)d_in[1];
    const float* v  = (const float*)d_in[2];
    const float* ab = (const float*)d_in[3];
    const float* wq = (const float*)d_in[4];
    const float* bq = (const float*)d_in[5];
    const float* wk = (const float*)d_in[6];
    const float* bk = (const float*)d_in[7];
    const float* wv = (const float*)d_in[8];
    const float* bv = (const float*)d_in[9];
    const float* wo = (const float*)d_in[10];
    const float* bo = (const float*)d_in[11];
    float* out = (float*)d_out;

    cudaFuncSetAttribute(proj_kernel,  cudaFuncAttributeMaxDynamicSharedMemorySize, SMEM_GEMM_BYTES);
    cudaFuncSetAttribute(biasv_kernel, cudaFuncAttributeMaxDynamicSharedMemorySize, SMEM_GEMM_BYTES);
    cudaFuncSetAttribute(out_kernel,   cudaFuncAttributeMaxDynamicSharedMemorySize, SMEM_GEMM_BYTES);
    cudaFuncSetAttribute(attn_kernel,  cudaFuncAttributeMaxDynamicSharedMemorySize, SMEM_ATTN_BYTES);

    proj_kernel<<<dim3(SEQL / 128, VIEWS, 3), 256, SMEM_GEMM_BYTES>>>(
        q, k, v, wq, bq, wk, bk, wv, bv);
    biasv_kernel<<<dim3(SEQL / 128, VIEWS, 2), 256, SMEM_GEMM_BYTES>>>(ab);
    attn_kernel<<<dim3(SEQL / BQ, VIEWS), 128, SMEM_ATTN_BYTES>>>();
    out_kernel<<<dim3(SEQL / 128, HID / 128, 2), 256, SMEM_GEMM_BYTES>>>(wo);
    combine_kernel<<<(SEQL * HID / 4) / 256, 256>>>(bo, out);
}

// round 17
// speedup vs baseline: 1.2754x; 1.1479x over previous
#include <cuda_runtime.h>
#include <cuda_fp16.h>
#include <math.h>
#include <stdint.h>

#define VIEWS 8
#define SEQL  2048
#define HID   1024
#define ATT   128
#define SCALE 0.08838834764831845f   /* 1/sqrt(128) */

// ---------------- scratch (device globals: no allocations allowed) ----------
__device__ __align__(16) __half h_qh [VIEWS * SEQL * ATT];   // fp16 [v][s][a]
__device__ __align__(16) __half h_kh [VIEWS * SEQL * ATT];   // fp16 [v][s][a]
__device__ __align__(16) __half h_vh [VIEWS * SEQL * ATT];   // fp16 [v][s][a]
__device__ __align__(16) __half h_vhT[VIEWS * ATT * SEQL];   // fp16 [v][a][s]
__device__ __align__(16) __half h_wT [3 * ATT * HID];        // fp16 [n=128][k=1024]
__device__ __align__(16) __half h_woT[HID * HID];            // fp16 [n][k]
__device__ __align__(16) float g_x  [SEQL * HID];            // bias@V p0; then x
__device__ __align__(16) float g_x2 [SEQL * HID];            // bias@V p1; out p1
__device__ __align__(16) float g_tmp[SEQL * HID];            // out p0
__device__ __align__(16) float g_zero[ATT];

// ---------------------------------------------------------------------------
// helpers
// ---------------------------------------------------------------------------
__device__ __forceinline__ void mma_f16(float* d,
    uint32_t a0, uint32_t a1, uint32_t a2, uint32_t a3,
    uint32_t b0, uint32_t b1)
{
    asm volatile(
        "mma.sync.aligned.m16n8k16.row.col.f32.f16.f16.f32 "
        "{%0,%1,%2,%3},{%4,%5,%6,%7},{%8,%9},{%0,%1,%2,%3};\n"
        : "+f"(d[0]), "+f"(d[1]), "+f"(d[2]), "+f"(d[3])
        : "r"(a0), "r"(a1), "r"(a2), "r"(a3), "r"(b0), "r"(b1));
}
__device__ __forceinline__ uint32_t ldh(const __half* p) {
    return *(const uint32_t*)p;
}
__device__ __forceinline__ uint32_t packh2(float lo, float hi) {
    __half2 h = __floats2half2_rn(lo, hi);   // .x = lo, .y = hi
    return *(uint32_t*)&h;
}
__device__ __forceinline__ uint32_t smem_u32(const void* p) {
    uint32_t a;
    asm("{ .reg .u64 t; cvta.to.shared.u64 t, %1; cvt.u32.u64 %0, t; }"
        : "=r"(a) : "l"(p));
    return a;
}
__device__ __forceinline__ void cpasync16(uint32_t dst, const void* src) {
    asm volatile("cp.async.cg.shared.global [%0], [%1], 16;\n" :: "r"(dst), "l"(src));
}
#define CP_COMMIT() asm volatile("cp.async.commit_group;\n" ::: "memory")
#define CP_WAIT0()  asm volatile("cp.async.wait_group 0;\n"  ::: "memory")
#define CP_WAIT1()  asm volatile("cp.async.wait_group 1;\n"  ::: "memory")

// ============================================================================
// fp16 mma.sync GEMM, 128x128 block, 256 threads (8 warps, 4m x 2n),
// warp tile 32x64, BK=32.
//   A: fp32 gmem [m][k], converted in-flight (LDG float4 -> cvt -> STS), 2-slot.
//   BT: fp16 gmem [n][k] (pre-transposed), 3-stage cp.async.
// C = (A@B + bias) * mul.  HOUT: write fp16 (proj) else fp32.
// ============================================================================
#define ALD 40                       // A smem row stride (halves)
#define BLD 40                       // B smem row stride (halves)
#define ASTG (128 * ALD)
#define BSTG (128 * BLD)
#define SMEM_HG_BYTES ((2 * ASTG + 3 * BSTG) * 2)    // 51200

template<bool HOUT>
__device__ __forceinline__ void hgemm_128x128(
    const float* __restrict__ A, int lda,
    const __half* __restrict__ BT, int ldbt,
    const float* __restrict__ bias,
    void* Cv, int ldc, int Ktot, float mul)
{
    extern __shared__ __half hsm[];
    __half* Asm = hsm;
    __half* Bsm = hsm + 2 * ASTG;

    const int tid  = threadIdx.x;
    const int wid  = tid >> 5;
    const int lane = tid & 31;
    const int g    = lane >> 2;
    const int tig  = lane & 3;

    const int m0 = (wid & 3) * 32;
    const int n0 = (wid >> 2) * 64;

    const int niter = Ktot >> 5;

    auto ldA = [&](int it, float4* pa) {
        const int k0 = it << 5;
#pragma unroll
        for (int i = 0; i < 4; i++) {
            const int idx = tid + i * 256;
            const int r = idx >> 3, c = (idx & 7) << 2;
            pa[i] = *(const float4*)&A[(size_t)r * lda + k0 + c];
        }
    };
    auto stsA = [&](int slot, const float4* pa) {
        __half* As = Asm + slot * ASTG;
#pragma unroll
        for (int i = 0; i < 4; i++) {
            const int idx = tid + i * 256;
            const int r = idx >> 3, c = (idx & 7) << 2;
            const uint32_t u0 = packh2(pa[i].x, pa[i].y);
            const uint32_t u1 = packh2(pa[i].z, pa[i].w);
            *(uint2*)&As[r * ALD + c] = make_uint2(u0, u1);
        }
    };
    auto cpB = [&](int it) {
        const int k0 = it << 5;
        const uint32_t sB = smem_u32(Bsm + (it % 3) * BSTG);
#pragma unroll
        for (int i = 0; i < 2; i++) {
            const int idx = tid + i * 256;
            const int r = idx >> 2, c = (idx & 3) << 3;
            cpasync16(sB + (uint32_t)(r * BLD + c) * 2,
                      &BT[(size_t)r * ldbt + k0 + c]);
        }
        CP_COMMIT();
    };

    float acc[2][8][4];
#pragma unroll
    for (int mt = 0; mt < 2; mt++)
#pragma unroll
        for (int nt = 0; nt < 8; nt++)
#pragma unroll
            for (int i = 0; i < 4; i++) acc[mt][nt][i] = 0.f;

    float4 pa[2][4];
    ldA(0, pa[0]);
    ldA(1, pa[1]);
    stsA(0, pa[0]);
    cpB(0);
    if (niter > 1) cpB(1);

    for (int it = 0; it < niter; it++) {
        if (it + 1 < niter) CP_WAIT1(); else CP_WAIT0();
        __syncthreads();

        if (it + 2 < niter) cpB(it + 2);
        if (it + 1 < niter) stsA((it + 1) & 1, pa[(it + 1) & 1]);
        if (it + 2 < niter) ldA(it + 2, pa[it & 1]);

        const __half* As = Asm + (it & 1) * ASTG;
        const __half* Bs = Bsm + (it % 3) * BSTG;

#pragma unroll
        for (int ks = 0; ks < 32; ks += 16) {
            uint32_t a[2][4];
#pragma unroll
            for (int mt = 0; mt < 2; mt++) {
                const int r = m0 + mt * 16;
                a[mt][0] = ldh(&As[(r + g)     * ALD + ks + 2 * tig]);
                a[mt][1] = ldh(&As[(r + g + 8) * ALD + ks + 2 * tig]);
                a[mt][2] = ldh(&As[(r + g)     * ALD + ks + 2 * tig + 8]);
                a[mt][3] = ldh(&As[(r + g + 8) * ALD + ks + 2 * tig + 8]);
            }
#pragma unroll
            for (int nt = 0; nt < 8; nt++) {
                const int nc = n0 + nt * 8 + g;
                const uint32_t b0 = ldh(&Bs[nc * BLD + ks + 2 * tig]);
                const uint32_t b1 = ldh(&Bs[nc * BLD + ks + 2 * tig + 8]);
                mma_f16(acc[0][nt], a[0][0], a[0][1], a[0][2], a[0][3], b0, b1);
                mma_f16(acc[1][nt], a[1][0], a[1][1], a[1][2], a[1][3], b0, b1);
            }
        }
        __syncthreads();
    }

    // epilogue
#pragma unroll
    for (int mt = 0; mt < 2; mt++) {
        const int r = m0 + mt * 16;
#pragma unroll
        for (int nt = 0; nt < 8; nt++) {
            const int col = n0 + nt * 8 + tig * 2;
            const float b0 = bias[col], b1 = bias[col + 1];
            const float o00 = (acc[mt][nt][0] + b0) * mul;
            const float o01 = (acc[mt][nt][1] + b1) * mul;
            const float o10 = (acc[mt][nt][2] + b0) * mul;
            const float o11 = (acc[mt][nt][3] + b1) * mul;
            if (HOUT) {
                __half* C = (__half*)Cv;
                *(__half2*)&C[(size_t)(r + g)     * ldc + col] = __floats2half2_rn(o00, o01);
                *(__half2*)&C[(size_t)(r + g + 8) * ldc + col] = __floats2half2_rn(o10, o11);
            } else {
                float* C = (float*)Cv;
                *(float2*)&C[(size_t)(r + g)     * ldc + col] = make_float2(o00, o01);
                *(float2*)&C[(size_t)(r + g + 8) * ldc + col] = make_float2(o10, o11);
            }
        }
    }
}

// ---------------------------------------------------------------------------
// Prep: transpose + fp16-convert weights.  grid (32, 32, 4), block (32, 8).
// ---------------------------------------------------------------------------
__global__ void __launch_bounds__(256) prep_w_kernel(
    const float* __restrict__ wq, const float* __restrict__ wk,
    const float* __restrict__ wv, const float* __restrict__ wo)
{
    const int z = blockIdx.z;
    const float* src; __half* dst; int N;
    if (z < 3) {
        if (blockIdx.y >= 4) return;
        src = (z == 0) ? wq : (z == 1) ? wk : wv;
        dst = h_wT + (size_t)z * ATT * HID;
        N = ATT;
    } else {
        src = wo; dst = h_woT; N = HID;
    }
    __shared__ float t[32][33];
    const int tx = threadIdx.x, ty = threadIdx.y;
#pragma unroll
    for (int j = 0; j < 4; j++)
        t[ty + j * 8][tx] = src[(size_t)(blockIdx.x * 32 + ty + j * 8) * N + blockIdx.y * 32 + tx];
    __syncthreads();
#pragma unroll
    for (int j = 0; j < 4; j++)
        dst[(size_t)(blockIdx.y * 32 + ty + j * 8) * HID + blockIdx.x * 32 + tx] =
            __float2half_rn(t[tx][ty + j * 8]);
}

// ---------------------------------------------------------------------------
// Prep: transpose h_vh -> h_vhT.  grid (64, 4, 8 views), block (32, 8).
// ---------------------------------------------------------------------------
__global__ void __launch_bounds__(256) prep_vhT_kernel()
{
    const int view = blockIdx.z;
    const __half* src = h_vh + (size_t)view * SEQL * ATT;
    __half* dst = h_vhT + (size_t)view * ATT * SEQL;
    __shared__ __half t[32][34];
    const int tx = threadIdx.x, ty = threadIdx.y;
#pragma unroll
    for (int j = 0; j < 4; j++)
        t[ty + j * 8][tx] = src[(size_t)(blockIdx.x * 32 + ty + j * 8) * ATT + blockIdx.y * 32 + tx];
    __syncthreads();
#pragma unroll
    for (int j = 0; j < 4; j++)
        dst[(size_t)(blockIdx.y * 32 + ty + j * 8) * SEQL + blockIdx.x * 32 + tx] =
            t[tx][ty + j * 8];
}

// ---------------------------------------------------------------------------
// Kernel 1: QKV projection (fp16 out).  grid (16 Mtiles, 8 views, 3 proj)
// ---------------------------------------------------------------------------
__global__ void __launch_bounds__(256, 2) proj_kernel(
    const float* __restrict__ q, const float* __restrict__ k,
    const float* __restrict__ v,
    const float* __restrict__ bq, const float* __restrict__ bk,
    const float* __restrict__ bv)
{
    const int view = blockIdx.y;
    const int pz   = blockIdx.z;
    const float *A, *bias;
    __half* O;
    float mul = 1.0f;
    if (pz == 0)      { A = q; bias = bq; O = h_qh; mul = SCALE; }
    else if (pz == 1) { A = k; bias = bk; O = h_kh; }
    else              { A = v; bias = bv; O = h_vh; }

    const int row0 = blockIdx.x * 128;
    hgemm_128x128<true>(A + (size_t)view * SEQL * HID + (size_t)row0 * HID, HID,
                        h_wT + (size_t)pz * ATT * HID, HID, bias,
                        O + (size_t)view * SEQL * ATT + (size_t)row0 * ATT, ATT,
                        HID, mul);
}

// ---------------------------------------------------------------------------
// Kernel 1b: bias GEMM, K-split x2.  grid (16, 8, 2).
// ---------------------------------------------------------------------------
__global__ void __launch_bounds__(256, 2) biasv_kernel(const float* __restrict__ attn_bias)
{
    const int view = blockIdx.y;
    const int row0 = blockIdx.x * 128;
    const int h    = blockIdx.z;
    const int k0   = h * (SEQL / 2);
    const float* A  = attn_bias + (size_t)view * SEQL * SEQL + (size_t)row0 * SEQL + k0;
    const __half* B = h_vhT + (size_t)view * ATT * SEQL + k0;
    float* C = (h == 0 ? g_x : g_x2) + (size_t)row0 * HID + view * ATT;
    hgemm_128x128<false>(A, SEQL, B, SEQL, g_zero, C, HID, SEQL / 2, 1.0f);
}

// ---------------------------------------------------------------------------
// Kernel 2: fp16 FA2 attention, 128 threads (4 warps), BQ=64, BK=32,
//   double-buffered cp.async K (natural [s][a]) and V (from vhT [a][s]),
//   register softmax, P reused as fp16 A-frags with NO shuffles.
//   grid (32 q-tiles, 8 views) = 256 CTAs.
//   Epilogue: g_x = g_x + g_x2 + oacc/l.
// ---------------------------------------------------------------------------
#define BQ    64
#define BK    32
#define NT_KT (SEQL / BK)
#define QLD   136                 // Q/K row stride (halves)
#define VLD   40                  // V row stride (halves)
#define KSTG  (BK * QLD)
#define VSTG  (ATT * VLD)
#define SMEM_ATTN_BYTES ((BQ * QLD + 2 * KSTG + 2 * VSTG) * 2)   // 55296

__global__ void __launch_bounds__(128, 3) attn_kernel()
{
    extern __shared__ __half hsm[];
    __half* Qs = hsm;                    // [64][QLD]
    __half* Kb = Qs + BQ * QLD;          // 2 x [32][QLD]
    __half* Vb = Kb + 2 * KSTG;          // 2 x [128][VLD]  (rows = a, cols = s)

    const int tid  = threadIdx.x;
    const int wid  = tid >> 5;
    const int lane = tid & 31;
    const int g    = lane >> 2;
    const int tig  = lane & 3;

    const int view = blockIdx.y;
    const int q0   = blockIdx.x * BQ;

    const __half* qh  = h_qh  + (size_t)view * SEQL * ATT + (size_t)q0 * ATT;
    const __half* kh  = h_kh  + (size_t)view * SEQL * ATT;
    const __half* vhT = h_vhT + (size_t)view * ATT * SEQL;

    const uint32_t sQ = smem_u32(Qs);
    const uint32_t sK = smem_u32(Kb);
    const uint32_t sV = smem_u32(Vb);

    auto issueKV = [&](int it) {
        const int buf = it & 1;
        const __half* kbase = kh + (size_t)(it * BK) * ATT;
        const __half* vbase = vhT + it * BK;
#pragma unroll
        for (int i = 0; i < 4; i++) {
            const int idx = tid + i * 128;
            // K: 32 rows x 256B = 16 chunks/row
            const int kr = idx >> 4, kc = (idx & 15) << 3;
            cpasync16(sK + (uint32_t)(buf * KSTG + kr * QLD + kc) * 2,
                      &kbase[(size_t)kr * ATT + kc]);
            // V: 128 rows x 64B = 4 chunks/row
            const int vr = idx >> 2, vc = (idx & 3) << 3;
            cpasync16(sV + (uint32_t)(buf * VSTG + vr * VLD + vc) * 2,
                      &vbase[(size_t)vr * SEQL + vc]);
        }
        CP_COMMIT();
    };

    // prologue: group0 = Q + KV(0); group1 = KV(1)
    {
#pragma unroll
        for (int i = 0; i < 8; i++) {
            const int idx = tid + i * 128;          // 0..1023
            const int r = idx >> 4, c = (idx & 15) << 3;
            cpasync16(sQ + (uint32_t)(r * QLD + c) * 2, &qh[(size_t)r * ATT + c]);
        }
#pragma unroll
        for (int i = 0; i < 4; i++) {
            const int idx = tid + i * 128;
            const int kr = idx >> 4, kc = (idx & 15) << 3;
            cpasync16(sK + (uint32_t)(kr * QLD + kc) * 2, &kh[(size_t)kr * ATT + kc]);
            const int vr = idx >> 2, vc = (idx & 3) << 3;
            cpasync16(sV + (uint32_t)(vr * VLD + vc) * 2, &vhT[(size_t)vr * SEQL + vc]);
        }
        CP_COMMIT();
        issueKV(1);
    }

    const int m0 = wid * 16;

    float oacc[16][4];
#pragma unroll
    for (int nt = 0; nt < 16; nt++)
#pragma unroll
        for (int i = 0; i < 4; i++) oacc[nt][i] = 0.f;

    float mst0 = -3.0e38f, mst1 = -3.0e38f;
    float lst0 = 0.f,      lst1 = 0.f;

    for (int kt = 0; kt < NT_KT; kt++) {
        if (kt + 1 < NT_KT) CP_WAIT1(); else CP_WAIT0();
        __syncthreads();

        const __half* Ks = Kb + (kt & 1) * KSTG;
        const __half* Vs = Vb + (kt & 1) * VSTG;

        // ---- phase 1: S(16x32 per warp) = Q @ K^T  (8 x k16 steps) ----
        float sacc[4][4];
#pragma unroll
        for (int j = 0; j < 4; j++)
#pragma unroll
            for (int i = 0; i < 4; i++) sacc[j][i] = 0.f;

#pragma unroll
        for (int s16 = 0; s16 < 8; s16++) {
            const int kk = s16 * 16;
            const uint32_t a0 = ldh(&Qs[(m0 + g)     * QLD + kk + 2 * tig]);
            const uint32_t a1 = ldh(&Qs[(m0 + g + 8) * QLD + kk + 2 * tig]);
            const uint32_t a2 = ldh(&Qs[(m0 + g)     * QLD + kk + 2 * tig + 8]);
            const uint32_t a3 = ldh(&Qs[(m0 + g + 8) * QLD + kk + 2 * tig + 8]);
#pragma unroll
            for (int j = 0; j < 4; j++) {
                const int nr = j * 8 + g;
                const uint32_t b0 = ldh(&Ks[nr * QLD + kk + 2 * tig]);
                const uint32_t b1 = ldh(&Ks[nr * QLD + kk + 2 * tig + 8]);
                mma_f16(sacc[j], a0, a1, a2, a3, b0, b1);
            }
        }

        // ---- phase 2: register online softmax (fp32) ----
        {
            float mx0 = -3.0e38f, mx1 = -3.0e38f;
#pragma unroll
            for (int j = 0; j < 4; j++) {
                mx0 = fmaxf(mx0, fmaxf(sacc[j][0], sacc[j][1]));
                mx1 = fmaxf(mx1, fmaxf(sacc[j][2], sacc[j][3]));
            }
            mx0 = fmaxf(mx0, __shfl_xor_sync(0xffffffffu, mx0, 1));
            mx0 = fmaxf(mx0, __shfl_xor_sync(0xffffffffu, mx0, 2));
            mx1 = fmaxf(mx1, __shfl_xor_sync(0xffffffffu, mx1, 1));
            mx1 = fmaxf(mx1, __shfl_xor_sync(0xffffffffu, mx1, 2));

            const float mnew0 = fmaxf(mst0, mx0);
            const float mnew1 = fmaxf(mst1, mx1);
            const float corr0 = __expf(mst0 - mnew0);
            const float corr1 = __expf(mst1 - mnew1);
            mst0 = mnew0; mst1 = mnew1;

            float s0 = 0.f, s1 = 0.f;
#pragma unroll
            for (int j = 0; j < 4; j++) {
                float e;
                e = __expf(sacc[j][0] - mnew0); s0 += e; sacc[j][0] = e;
                e = __expf(sacc[j][1] - mnew0); s0 += e; sacc[j][1] = e;
                e = __expf(sacc[j][2] - mnew1); s1 += e; sacc[j][2] = e;
                e = __expf(sacc[j][3] - mnew1); s1 += e; sacc[j][3] = e;
            }
            s0 += __shfl_xor_sync(0xffffffffu, s0, 1);
            s0 += __shfl_xor_sync(0xffffffffu, s0, 2);
            s1 += __shfl_xor_sync(0xffffffffu, s1, 1);
            s1 += __shfl_xor_sync(0xffffffffu, s1, 2);
            lst0 = lst0 * corr0 + s0;
            lst1 = lst1 * corr1 + s1;

#pragma unroll
            for (int nt = 0; nt < 16; nt++) {
                oacc[nt][0] *= corr0; oacc[nt][1] *= corr0;
                oacc[nt][2] *= corr1; oacc[nt][3] *= corr1;
            }
        }

        // ---- phase 3: oacc += P @ V  (P D-frags -> fp16 A-frags, no shfl) ----
#pragma unroll
        for (int jk = 0; jk < 2; jk++) {
            const int ks = jk * 16;
            const uint32_t a0 = packh2(sacc[2 * jk][0],     sacc[2 * jk][1]);
            const uint32_t a1 = packh2(sacc[2 * jk][2],     sacc[2 * jk][3]);
            const uint32_t a2 = packh2(sacc[2 * jk + 1][0], sacc[2 * jk + 1][1]);
            const uint32_t a3 = packh2(sacc[2 * jk + 1][2], sacc[2 * jk + 1][3]);
#pragma unroll
            for (int nt = 0; nt < 16; nt++) {
                const int nc = nt * 8 + g;
                const uint32_t b0 = ldh(&Vs[nc * VLD + ks + 2 * tig]);
                const uint32_t b1 = ldh(&Vs[nc * VLD + ks + 2 * tig + 8]);
                mma_f16(oacc[nt], a0, a1, a2, a3, b0, b1);
            }
        }

        __syncthreads();
        if (kt + 2 < NT_KT) issueKV(kt + 2);
    }

    // ---- epilogue: g_x = g_x + g_x2 + oacc / l ----
    const float inv0 = 1.f / lst0;
    const float inv1 = 1.f / lst1;
    const size_t off0 = (size_t)(q0 + m0 + g)     * HID + view * ATT;
    const size_t off1 = (size_t)(q0 + m0 + g + 8) * HID + view * ATT;
#pragma unroll
    for (int nt = 0; nt < 16; nt++) {
        const int col = nt * 8 + tig * 2;
        float2 x0 = *(const float2*)&g_x [off0 + col];
        float2 y0 = *(const float2*)&g_x2[off0 + col];
        float2 x1 = *(const float2*)&g_x [off1 + col];
        float2 y1 = *(const float2*)&g_x2[off1 + col];
        x0.x += y0.x + oacc[nt][0] * inv0;  x0.y += y0.y + oacc[nt][1] * inv0;
        x1.x += y1.x + oacc[nt][2] * inv1;  x1.y += y1.y + oacc[nt][3] * inv1;
        *(float2*)&g_x[off0 + col] = x0;
        *(float2*)&g_x[off1 + col] = x1;
    }
}

// ---------------------------------------------------------------------------
// Kernel 3: out partials, K-split x2.  grid (16, 8, 2).
// ---------------------------------------------------------------------------
__global__ void __launch_bounds__(256, 2) out_kernel()
{
    const int row0 = blockIdx.x * 128;
    const int col0 = blockIdx.y * 128;
    const int h    = blockIdx.z;
    const int k0   = h * (HID / 2);
    float* C = (h == 0 ? g_tmp : g_x2) + (size_t)row0 * HID + col0;
    hgemm_128x128<false>(g_x + (size_t)row0 * HID + k0, HID,
                         h_woT + (size_t)col0 * HID + k0, HID, g_zero,
                         C, HID, HID / 2, 1.0f);
}

// ---------------------------------------------------------------------------
// Kernel 3b: out = t0 + t1 + bo.
// ---------------------------------------------------------------------------
__global__ void __launch_bounds__(256) combine_kernel(
    const float* __restrict__ bo, float* __restrict__ out)
{
    const int idx = blockIdx.x * 256 + threadIdx.x;
    const int c4  = (idx & (HID / 4 - 1)) * 4;
    const float4 t0 = *(const float4*)&g_tmp[(size_t)idx * 4];
    const float4 t1 = *(const float4*)&g_x2 [(size_t)idx * 4];
    const float4 bb = *(const float4*)&bo[c4];
    float4 o;
    o.x = t0.x + t1.x + bb.x;
    o.y = t0.y + t1.y + bb.y;
    o.z = t0.z + t1.z + bb.z;
    o.w = t0.w + t1.w + bb.w;
    *(float4*)&out[(size_t)idx * 4] = o;
}

// ---------------------------------------------------------------------------
extern "C" void kernel_launch(void* const* d_in, const int* in_sizes, int n_in,
                              void* d_out, int out_size)
{
    const float* q  = (const float*)d_in[0];
    const float* k  = (const float*)d_in[1];
    const float* v  = (const float*)d_in[2];
    const float* ab = (const float*)d_in[3];
    const float* wq = (const float*)d_in[4];
    const float* bq = (const float*)d_in[5];
    const float* wk = (const float*)d_in[6];
    const float* bk = (const float*)d_in[7];
    const float* wv = (const float*)d_in[8];
    const float* bv = (const float*)d_in[9];
    const float* wo = (const float*)d_in[10];
    const float* bo = (const float*)d_in[11];
    float* out = (float*)d_out;

    cudaFuncSetAttribute(proj_kernel,  cudaFuncAttributeMaxDynamicSharedMemorySize, SMEM_HG_BYTES);
    cudaFuncSetAttribute(biasv_kernel, cudaFuncAttributeMaxDynamicSharedMemorySize, SMEM_HG_BYTES);
    cudaFuncSetAttribute(out_kernel,   cudaFuncAttributeMaxDynamicSharedMemorySize, SMEM_HG_BYTES);
    cudaFuncSetAttribute(attn_kernel,  cudaFuncAttributeMaxDynamicSharedMemorySize, SMEM_ATTN_BYTES);

    prep_w_kernel<<<dim3(32, 32, 4), dim3(32, 8)>>>(wq, wk, wv, wo);
    proj_kernel<<<dim3(SEQL / 128, VIEWS, 3), 256, SMEM_HG_BYTES>>>(q, k, v, bq, bk, bv);
    prep_vhT_kernel<<<dim3(64, 4, VIEWS), dim3(32, 8)>>>();
    biasv_kernel<<<dim3(SEQL / 128, VIEWS, 2), 256, SMEM_HG_BYTES>>>(ab);
    attn_kernel<<<dim3(SEQL / BQ, VIEWS), 128, SMEM_ATTN_BYTES>>>();
    out_kernel<<<dim3(SEQL / 128, HID / 128, 2), 256, SMEM_HG_BYTES>>>();
    combine_kernel<<<(SEQL * HID / 4) / 256, 256>>>(bo, out);
}